// round 2
// baseline (speedup 1.0000x reference)
#include <cuda_runtime.h>
#include <math.h>

#define DM 256
#define HEADS 8
#define DH 32
#define LEVELS 4
#define POINTS 4
#define DFFN 1024
#define BATCH 8
#define NQ 300
#define NC 16
#define LQ (NQ*NC)          // 4800
#define TOK (BATCH*LQ)      // 38400
#define LEN_IN 5440
#define VROWS (BATCH*LEN_IN) // 43520

// ---------------- scratch (static device memory; no runtime allocation) ----
__device__ float g_t[TOK*DM];        // evolving residual stream
__device__ float g_q[TOK*DM];        // t + query_pos (also reused for sampled CA out)
__device__ float g_x[TOK*DM];        // generic temp
__device__ float g_y[TOK*DM];        // generic temp
__device__ float g_big[TOK*DFFN];    // qkv (768 cols used) / FFN hidden (1024 cols)
__device__ float g_val[VROWS*DM];    // projected value
__device__ float g_attw[TOK*HEADS*LEVELS*POINTS];   // TOK * 128

// ---------------- generic SGEMM: C[M,N] = A[M,K] @ W[N,K]^T + bias ---------
// Requires: M % 64 == 0, N % 64 == 0, K % 16 == 0 (true for all calls here).
__global__ void gemm_kernel(const float* __restrict__ A,
                            const float* __restrict__ W,
                            const float* __restrict__ bias,
                            float* __restrict__ C,
                            int M, int N, int K, int ldc, int relu)
{
    __shared__ float As[16][64];
    __shared__ float Bs[16][64];
    int tid = threadIdx.x;                   // 256 threads
    int bm = blockIdx.y << 6, bn = blockIdx.x << 6;
    int tx = tid & 15, ty = tid >> 4;
    int m0 = ty << 2, n0 = tx << 2;
    int lr = tid >> 2;                       // 0..63
    int lk = (tid & 3) << 2;                 // 0,4,8,12

    const float* Ap = A + (size_t)(bm + lr) * K + lk;
    const float* Wp = W + (size_t)(bn + lr) * K + lk;

    float acc[4][4];
#pragma unroll
    for (int i = 0; i < 4; i++)
#pragma unroll
        for (int j = 0; j < 4; j++) acc[i][j] = 0.f;

    for (int k0 = 0; k0 < K; k0 += 16) {
        float4 av = *(const float4*)(Ap + k0);
        float4 wv = *(const float4*)(Wp + k0);
        __syncthreads();
        As[lk + 0][lr] = av.x; As[lk + 1][lr] = av.y;
        As[lk + 2][lr] = av.z; As[lk + 3][lr] = av.w;
        Bs[lk + 0][lr] = wv.x; Bs[lk + 1][lr] = wv.y;
        Bs[lk + 2][lr] = wv.z; Bs[lk + 3][lr] = wv.w;
        __syncthreads();
#pragma unroll
        for (int k = 0; k < 16; k++) {
            float4 a = *(const float4*)&As[k][m0];
            float4 b = *(const float4*)&Bs[k][n0];
            acc[0][0] += a.x*b.x; acc[0][1] += a.x*b.y; acc[0][2] += a.x*b.z; acc[0][3] += a.x*b.w;
            acc[1][0] += a.y*b.x; acc[1][1] += a.y*b.y; acc[1][2] += a.y*b.z; acc[1][3] += a.y*b.w;
            acc[2][0] += a.z*b.x; acc[2][1] += a.z*b.y; acc[2][2] += a.z*b.z; acc[2][3] += a.z*b.w;
            acc[3][0] += a.w*b.x; acc[3][1] += a.w*b.y; acc[3][2] += a.w*b.z; acc[3][3] += a.w*b.w;
        }
    }

#pragma unroll
    for (int i = 0; i < 4; i++) {
        int m = bm + m0 + i;
        if (m >= M) continue;
#pragma unroll
        for (int j = 0; j < 4; j++) {
            int n = bn + n0 + j;
            float v = acc[i][j] + bias[n];
            if (relu) v = fmaxf(v, 0.f);
            C[(size_t)m * ldc + n] = v;
        }
    }
}

// ---------------- elementwise: q = a + b, optionally t = a ------------------
__global__ void add_copy_kernel(const float* __restrict__ a,
                                const float* __restrict__ b,
                                float* __restrict__ q,
                                float* __restrict__ t, int n)
{
    int i = blockIdx.x * blockDim.x + threadIdx.x;
    if (i < n) {
        float av = a[i];
        q[i] = av + b[i];
        if (t) t[i] = av;
    }
}

// ---------------- zero masked value rows -----------------------------------
__global__ void mask_kernel(float* __restrict__ val,
                            const unsigned char* __restrict__ mask, long n)
{
    long i = (long)blockIdx.x * blockDim.x + threadIdx.x;
    if (i < n) {
        if (mask[i >> 8]) val[i] = 0.f;
    }
}

// ---------------- self-attention over 16-token sequences --------------------
// one block (128 threads) per sequence; thread = (head, token)
__global__ void self_attn_kernel(const float* __restrict__ qkv,
                                 float* __restrict__ out)
{
    __shared__ float sQ[NC][DM];
    __shared__ float sK[NC][DM];
    __shared__ float sV[NC][DM];
    int s = blockIdx.x;
    int tid = threadIdx.x;
    const float* base = qkv + (size_t)s * NC * 768;
    for (int idx = tid; idx < NC * DM; idx += 128) {
        int i = idx >> 8, c = idx & 255;
        sQ[i][c] = base[i * 768 + c];
        sK[i][c] = base[i * 768 + 256 + c];
        sV[i][c] = base[i * 768 + 512 + c];
    }
    __syncthreads();

    int h = tid >> 4, i = tid & 15;
    const float scale = 0.1767766952966369f;  // 1/sqrt(32)
    float sc[NC];
    float mx = -1e30f;
#pragma unroll
    for (int j = 0; j < NC; j++) {
        float acc = 0.f;
#pragma unroll
        for (int d = 0; d < DH; d++) acc += sQ[i][h*DH + d] * sK[j][h*DH + d];
        acc *= scale;
        sc[j] = acc;
        mx = fmaxf(mx, acc);
    }
    float sum = 0.f;
#pragma unroll
    for (int j = 0; j < NC; j++) { sc[j] = expf(sc[j] - mx); sum += sc[j]; }
    float inv = 1.f / sum;
#pragma unroll
    for (int d = 0; d < DH; d++) {
        float acc = 0.f;
#pragma unroll
        for (int j = 0; j < NC; j++) acc += sc[j] * sV[j][h*DH + d];
        out[((size_t)s * NC + i) * DM + h*DH + d] = acc * inv;
    }
}

// ---------------- add + layernorm ------------------------------------------
__global__ void add_ln_kernel(const float* __restrict__ a,
                              const float* __restrict__ b,
                              const float* __restrict__ w,
                              const float* __restrict__ bb,
                              float* __restrict__ out)
{
    __shared__ float sred[8];
    __shared__ float smean, svar;
    int row = blockIdx.x, tid = threadIdx.x;    // 256 threads
    size_t idx = (size_t)row * DM + tid;
    float x = a[idx] + b[idx];
    float v = x;
#pragma unroll
    for (int o = 16; o; o >>= 1) v += __shfl_xor_sync(0xffffffffu, v, o);
    if ((tid & 31) == 0) sred[tid >> 5] = v;
    __syncthreads();
    if (tid == 0) {
        float s = 0.f;
#pragma unroll
        for (int k = 0; k < 8; k++) s += sred[k];
        smean = s * (1.f / DM);
    }
    __syncthreads();
    float d = x - smean;
    v = d * d;
#pragma unroll
    for (int o = 16; o; o >>= 1) v += __shfl_xor_sync(0xffffffffu, v, o);
    if ((tid & 31) == 0) sred[tid >> 5] = v;
    __syncthreads();
    if (tid == 0) {
        float s = 0.f;
#pragma unroll
        for (int k = 0; k < 8; k++) s += sred[k];
        svar = s * (1.f / DM);
    }
    __syncthreads();
    out[idx] = d * rsqrtf(svar + 1e-5f) * w[tid] + bb[tid];
}

// ---------------- deformable sampling ---------------------------------------
// one block (256 threads) per query token; warp = head, lane = channel.
// Per head: LEVELS*POINTS = 16 attention weights, 16 (x,y) offsets.
__global__ void deform_kernel(const float* __restrict__ off,
                              const float* __restrict__ attw,
                              const float* __restrict__ refp,
                              const float* __restrict__ val,
                              float* __restrict__ out)
{
    __shared__ float saw[HEADS][16];
    int token = blockIdx.x;
    int bidx  = token / LQ;
    int tid = threadIdx.x;
    int h = tid >> 5, lane = tid & 31;
    int j = lane & 15;   // weight index 0..15 (duplicated in upper half-warp)

    // per-head softmax over L*P = 16 weights
    float w = attw[(size_t)token * (HEADS*16) + h*16 + j];
    float mx = w;
#pragma unroll
    for (int o = 8; o; o >>= 1) mx = fmaxf(mx, __shfl_xor_sync(0xffffffffu, mx, o));
    float e = expf(w - mx);
    float s = e;
#pragma unroll
    for (int o = 8; o; o >>= 1) s += __shfl_xor_sync(0xffffffffu, s, o);
    if (lane < 16) saw[h][lane] = e / s;
    __syncwarp();

    const int Hs[4]     = {64, 32, 16, 8};
    const int Ws[4]     = {64, 32, 16, 8};
    const int starts[4] = {0, 4096, 5120, 5376};

    const float* offp = off + (size_t)token * DM + h * 32;   // (l*4+p)*2+xy
    const float* refb = refp + (size_t)token * (LEVELS*2);
    const float* vb = val + ((size_t)bidx * LEN_IN) * DM + h * DH + lane;

    float acc = 0.f;
#pragma unroll
    for (int l = 0; l < LEVELS; l++) {
        int H_ = Hs[l], W_ = Ws[l];
        float rx = refb[l*2 + 0], ry = refb[l*2 + 1];
        const float* vlev = vb + (size_t)starts[l] * DM;
#pragma unroll
        for (int p = 0; p < POINTS; p++) {
            float ox = offp[(l*4 + p)*2 + 0];
            float oy = offp[(l*4 + p)*2 + 1];
            float gx = (rx + ox / W_) * W_ - 0.5f;
            float gy = (ry + oy / H_) * H_ - 0.5f;
            float fx = floorf(gx), fy = floorf(gy);
            int x0 = (int)fx, y0 = (int)fy;
            float ax = gx - fx, ay = gy - fy;
            float aw = saw[h][l*4 + p];
            bool xin0 = (x0 >= 0) && (x0 < W_);
            bool xin1 = (x0 + 1 >= 0) && (x0 + 1 < W_);
            bool yin0 = (y0 >= 0) && (y0 < H_);
            bool yin1 = (y0 + 1 >= 0) && (y0 + 1 < H_);
            float v00 = (xin0 && yin0) ? vlev[(size_t)(y0*W_ + x0) * DM] : 0.f;
            float v01 = (xin1 && yin0) ? vlev[(size_t)(y0*W_ + x0 + 1) * DM] : 0.f;
            float v10 = (xin0 && yin1) ? vlev[(size_t)((y0+1)*W_ + x0) * DM] : 0.f;
            float v11 = (xin1 && yin1) ? vlev[(size_t)((y0+1)*W_ + x0 + 1) * DM] : 0.f;
            float sample = v00*(1.f-ax)*(1.f-ay) + v01*ax*(1.f-ay)
                         + v10*(1.f-ax)*ay       + v11*ax*ay;
            acc += aw * sample;
        }
    }
    out[(size_t)token * DM + h * DH + lane] = acc;
}

// ---------------------------------------------------------------------------
extern "C" void kernel_launch(void* const* d_in, const int* in_sizes, int n_in,
                              void* d_out, int out_size)
{
    const float* tgt   = (const float*)d_in[0];
    const float* qpos  = (const float*)d_in[1];
    const float* refp  = (const float*)d_in[2];
    const float* src   = (const float*)d_in[3];
    const unsigned char* mask = (const unsigned char*)d_in[6];
    const float* sa_in_w  = (const float*)d_in[7];
    const float* sa_in_b  = (const float*)d_in[8];
    const float* sa_out_w = (const float*)d_in[9];
    const float* sa_out_b = (const float*)d_in[10];
    const float* norm2_w  = (const float*)d_in[11];
    const float* norm2_b  = (const float*)d_in[12];
    const float* ca_value_w = (const float*)d_in[13];
    const float* ca_value_b = (const float*)d_in[14];
    const float* ca_off_w   = (const float*)d_in[15];
    const float* ca_off_b   = (const float*)d_in[16];
    const float* ca_attw_w  = (const float*)d_in[17];
    const float* ca_attw_b  = (const float*)d_in[18];
    const float* ca_out_w   = (const float*)d_in[19];
    const float* ca_out_b   = (const float*)d_in[20];
    const float* norm1_w    = (const float*)d_in[21];
    const float* norm1_b    = (const float*)d_in[22];
    const float* lin1_w     = (const float*)d_in[23];
    const float* lin1_b     = (const float*)d_in[24];
    const float* lin2_w     = (const float*)d_in[25];
    const float* lin2_b     = (const float*)d_in[26];
    const float* norm3_w    = (const float*)d_in[27];
    const float* norm3_b    = (const float*)d_in[28];
    float* out = (float*)d_out;

    float *gt, *gq, *gx, *gy, *gbig, *gval, *gattw;
    cudaGetSymbolAddress((void**)&gt,   g_t);
    cudaGetSymbolAddress((void**)&gq,   g_q);
    cudaGetSymbolAddress((void**)&gx,   g_x);
    cudaGetSymbolAddress((void**)&gy,   g_y);
    cudaGetSymbolAddress((void**)&gbig, g_big);
    cudaGetSymbolAddress((void**)&gval, g_val);
    cudaGetSymbolAddress((void**)&gattw, g_attw);

    const int nTD = TOK * DM;   // 9,830,400

    // ---- stage 1: self-attention -------------------------------------------
    // q = tgt + qpos ; t = tgt
    add_copy_kernel<<<(nTD + 255) / 256, 256>>>(tgt, qpos, gq, gt, nTD);
    // QK projection (packed rows 0..511 of sa_in_w), from q
    {
        dim3 grid(512 / 64, TOK / 64);
        gemm_kernel<<<grid, 256>>>(gq, sa_in_w, sa_in_b, gbig, TOK, 512, DM, 768, 0);
    }
    // V projection (rows 512..767), from t
    {
        dim3 grid(256 / 64, TOK / 64);
        gemm_kernel<<<grid, 256>>>(gt, sa_in_w + (size_t)512 * DM, sa_in_b + 512,
                                   gbig + 512, TOK, 256, DM, 768, 0);
    }
    self_attn_kernel<<<BATCH * NQ, 128>>>(gbig, gx);
    {
        dim3 grid(256 / 64, TOK / 64);
        gemm_kernel<<<grid, 256>>>(gx, sa_out_w, sa_out_b, gy, TOK, 256, DM, 256, 0);
    }
    add_ln_kernel<<<TOK, 256>>>(gt, gy, norm2_w, norm2_b, gt);

    // ---- stage 2: deformable cross-attention -------------------------------
    add_copy_kernel<<<(nTD + 255) / 256, 256>>>(gt, qpos, gq, (float*)0, nTD);
    {
        dim3 grid(256 / 64, VROWS / 64);
        gemm_kernel<<<grid, 256>>>(src, ca_value_w, ca_value_b, gval, VROWS, 256, DM, 256, 0);
    }
    {
        long n = (long)VROWS * DM;
        mask_kernel<<<(unsigned)((n + 255) / 256), 256>>>(gval, mask, n);
    }
    {
        dim3 grid(256 / 64, TOK / 64);
        gemm_kernel<<<grid, 256>>>(gq, ca_off_w, ca_off_b, gx, TOK, 256, DM, 256, 0);
    }
    {
        dim3 grid(128 / 64, TOK / 64);
        gemm_kernel<<<grid, 256>>>(gq, ca_attw_w, ca_attw_b, gattw, TOK, 128, DM, 128, 0);
    }
    deform_kernel<<<TOK, 256>>>(gx, gattw, refp, gval, gq);
    {
        dim3 grid(256 / 64, TOK / 64);
        gemm_kernel<<<grid, 256>>>(gq, ca_out_w, ca_out_b, gx, TOK, 256, DM, 256, 0);
    }
    add_ln_kernel<<<TOK, 256>>>(gt, gx, norm1_w, norm1_b, gt);

    // ---- stage 3: FFN ------------------------------------------------------
    {
        dim3 grid(DFFN / 64, TOK / 64);
        gemm_kernel<<<grid, 256>>>(gt, lin1_w, lin1_b, gbig, TOK, DFFN, DM, DFFN, 1);
    }
    {
        dim3 grid(256 / 64, TOK / 64);
        gemm_kernel<<<grid, 256>>>(gbig, lin2_w, lin2_b, gx, TOK, 256, DFFN, 256, 0);
    }
    add_ln_kernel<<<TOK, 256>>>(gt, gx, norm3_w, norm3_b, out);
}